// round 7
// baseline (speedup 1.0000x reference)
#include <cuda_runtime.h>
#include <cstdint>

// 3x3 conv, stride 1, pad 1, NCHW fp32. B=8, CIN=COUT=16, H=W=1024.
// v2: no swizzle; PITCH=72 (16B-aligned rows); input window via LDS.128/LDS.64
// with immediate offsets (zero inner-loop address ALU); even pixel-pairs come
// free from float4 register pairs, only 4 odd pairs packed per row.
// Block: 16 rows x 64 cols spatial tile, all 16 cout.
// 256 threads = 2 cout-groups (8 cout each) x 128 positions (16 rows x 8 xgroups).

#define CIN   16
#define COUT  16
#define Hh    1024
#define Ww    1024
#define Bb    8

#define TH    16          // output rows per block
#define TW    64          // output cols per block
#define VEC   8           // pixels per thread
#define NCO   8           // couts per thread group
#define THREADS 256

#define IN_ROWS  (TH + 2)         // 18
#define IN_COLS  (TW + 2)         // 66 logical cols (lc 0..65), lc = x - x_base + 1
#define PITCH    72               // 72*4 = 288 bytes per row, multiple of 16 (LDS.128 align)
#define SIN_FLOATS (CIN * IN_ROWS * PITCH)          // 16*18*72 = 20736
#define SW_FLOAT2  (CIN * COUT * 9)                 // 2304
#define SMEM_BYTES (SIN_FLOATS * 4 + SW_FLOAT2 * 8) // 82944 + 18432 = 101376

typedef unsigned long long ull;

__device__ __forceinline__ void fma2(ull& d, ull a, ull b) {
    asm("fma.rn.f32x2 %0, %1, %2, %3;" : "=l"(d) : "l"(a), "l"(b), "l"(d));
}
__device__ __forceinline__ ull pack2(float lo, float hi) {
    ull r;
    asm("mov.b64 %0, {%1, %2};" : "=l"(r) : "f"(lo), "f"(hi));
    return r;
}
__device__ __forceinline__ void unpack2(ull v, float& lo, float& hi) {
    asm("mov.b64 {%0, %1}, %2;" : "=f"(lo), "=f"(hi) : "l"(v));
}

union U4 { float4 f; ull u[2]; };
union U2 { float2 f; ull u; };

__global__ __launch_bounds__(THREADS, 2)
void conv3x3_kernel(const float* __restrict__ x,
                    const float* __restrict__ w,
                    float* __restrict__ out)
{
    extern __shared__ float smem[];
    float* s_in = smem;                                  // [ci][row][PITCH]
    float2* s_w = (float2*)(smem + SIN_FLOATS);          // [ci][co][9] duplicated (w,w)

    const int t  = threadIdx.x;
    const int bx = blockIdx.x;       // 0..15  -> x_base
    const int by = blockIdx.y;       // 0..63  -> y_base
    const int b  = blockIdx.z;       // batch
    const int x_base = bx * TW;
    const int y_base = by * TH;

    // ---- stage weights: s_w[ci][co][k] = (W[co][ci][k], W[co][ci][k]) ----
    for (int i = t; i < SW_FLOAT2; i += THREADS) {
        int ci = i / (COUT * 9);
        int r  = i - ci * (COUT * 9);
        int co = r / 9;
        int k  = r - co * 9;
        float wv = w[((co * CIN + ci) * 9) + k];
        s_w[(ci * COUT + co) * 9 + k] = make_float2(wv, wv);
    }

    // ---- stage input: 16 ci x 18 rows x 66 cols, zero-padded halo ----
    const int TOT = CIN * IN_ROWS * IN_COLS;             // 19008
    for (int i = t; i < TOT; i += THREADS) {
        int ci  = i / (IN_ROWS * IN_COLS);
        int rem = i - ci * (IN_ROWS * IN_COLS);
        int r   = rem / IN_COLS;
        int lc  = rem - r * IN_COLS;
        int gy  = y_base + r - 1;
        int gx  = x_base + lc - 1;
        float v = 0.0f;
        if ((unsigned)gy < (unsigned)Hh && (unsigned)gx < (unsigned)Ww)
            v = x[(((size_t)b * CIN + ci) * Hh + gy) * Ww + gx];
        s_in[(ci * IN_ROWS + r) * PITCH + lc] = v;
    }
    __syncthreads();

    // ---- thread mapping ----
    const int grp = t >> 7;          // 0/1 -> cout half
    const int p   = t & 127;
    const int ty  = p >> 3;          // 0..15 output row in tile
    const int xg  = p & 7;           // 0..7 x-group
    const int x0  = xg * VEC;        // tile-local first pixel; window lc = x0 .. x0+9
    const int co0 = grp * NCO;

    ull acc[NCO][4];
    #pragma unroll
    for (int c = 0; c < NCO; c++)
        #pragma unroll
        for (int q = 0; q < 4; q++) acc[c][q] = 0ull;

    #pragma unroll 1
    for (int ci = 0; ci < CIN; ci++) {
        const float* in_ci = &s_in[ci * IN_ROWS * PITCH + x0];
        const float2* w_ci = &s_w[(ci * COUT + co0) * 9];
        #pragma unroll
        for (int ry = 0; ry < 3; ry++) {
            const float* row = in_ci + (ty + ry) * PITCH;
            // window v[0..9] = row[0..9], 16B-aligned base (x0 multiple of 8)
            U4 va, vb; U2 vc;
            va.f = *(const float4*)(row);        // v0..v3
            vb.f = *(const float4*)(row + 4);    // v4..v7
            vc.f = *(const float2*)(row + 8);    // v8,v9
            ull pr[9];
            pr[0] = va.u[0];                     // (v0,v1) free
            pr[2] = va.u[1];                     // (v2,v3) free
            pr[4] = vb.u[0];                     // (v4,v5) free
            pr[6] = vb.u[1];                     // (v6,v7) free
            pr[8] = vc.u;                        // (v8,v9) free
            pr[1] = pack2(va.f.y, va.f.z);       // (v1,v2)
            pr[3] = pack2(va.f.w, vb.f.x);       // (v3,v4)
            pr[5] = pack2(vb.f.y, vb.f.z);       // (v5,v6)
            pr[7] = pack2(vb.f.w, vc.f.x);       // (v7,v8)
            #pragma unroll
            for (int c = 0; c < NCO; c++) {
                const ull* wp = (const ull*)&w_ci[c * 9 + ry * 3];
                #pragma unroll
                for (int kx = 0; kx < 3; kx++) {
                    ull w2 = wp[kx];
                    #pragma unroll
                    for (int q = 0; q < 4; q++)
                        fma2(acc[c][q], pr[kx + 2 * q], w2);
                }
            }
        }
    }

    // ---- write back: float4 stores, 8 lanes x 16B contiguous ----
    const int oy = y_base + ty;
    const int ox = x_base + x0;
    #pragma unroll
    for (int c = 0; c < NCO; c++) {
        float* op = &out[(((size_t)b * COUT + (co0 + c)) * Hh + oy) * Ww + ox];
        float r0, r1, r2, r3, r4, r5, r6, r7;
        unpack2(acc[c][0], r0, r1);
        unpack2(acc[c][1], r2, r3);
        unpack2(acc[c][2], r4, r5);
        unpack2(acc[c][3], r6, r7);
        ((float4*)op)[0] = make_float4(r0, r1, r2, r3);
        ((float4*)op)[1] = make_float4(r4, r5, r6, r7);
    }
}

extern "C" void kernel_launch(void* const* d_in, const int* in_sizes, int n_in,
                              void* d_out, int out_size)
{
    const float* x = (const float*)d_in[0];
    const float* w = (const float*)d_in[1];
    float* out = (float*)d_out;

    // Unconditional (idempotent, not stream-ordered, graph-capture safe).
    cudaFuncSetAttribute(conv3x3_kernel,
                         cudaFuncAttributeMaxDynamicSharedMemorySize,
                         SMEM_BYTES);

    dim3 grid(Ww / TW, Hh / TH, Bb);   // (16, 64, 8)
    conv3x3_kernel<<<grid, THREADS, SMEM_BYTES>>>(x, w, out);
}

// round 8
// speedup vs baseline: 1.0336x; 1.0336x over previous
#include <cuda_runtime.h>
#include <cstdint>

// 3x3 conv, stride 1, pad 1, NCHW fp32. B=8, CIN=COUT=16, H=W=1024.
// v3: occupancy-oriented. Tile 8x64, NCO=4 (acc 32 regs), CIN staged in two
// 8-ci halves -> 41.4KB static SMEM, __launch_bounds__(256,3) caps regs at 85
// -> 3 blocks/SM = 24 warps (6/SMSP) for latency hiding.

#define CIN   16
#define COUT  16
#define Hh    1024
#define Ww    1024
#define Bb    8

#define TH    8           // output rows per block
#define TW    64          // output cols per block
#define VEC   8           // pixels per thread
#define NCO   4           // couts per thread group
#define THREADS 256

#define HALF_CI  8
#define IN_ROWS  (TH + 2)         // 10
#define IN_COLS  (TW + 2)         // 66, lc = gx - x_base + 1
#define PITCH    72               // 288B rows, 16B multiple for LDS.128
#define SIN_FLOATS (HALF_CI * IN_ROWS * PITCH)   // 5760 (23040 B)
#define SW_FLOAT2  (CIN * COUT * 9)              // 2304  (18432 B)

typedef unsigned long long ull;

__device__ __forceinline__ void fma2(ull& d, ull a, ull b) {
    asm("fma.rn.f32x2 %0, %1, %2, %3;" : "=l"(d) : "l"(a), "l"(b), "l"(d));
}
__device__ __forceinline__ ull pack2(float lo, float hi) {
    ull r;
    asm("mov.b64 %0, {%1, %2};" : "=l"(r) : "f"(lo), "f"(hi));
    return r;
}
__device__ __forceinline__ void unpack2(ull v, float& lo, float& hi) {
    asm("mov.b64 {%0, %1}, %2;" : "=f"(lo), "=f"(hi) : "l"(v));
}

union U4 { float4 f; ull u[2]; };
union U2 { float2 f; ull u; };

__global__ __launch_bounds__(THREADS, 3)
void conv3x3_kernel(const float* __restrict__ x,
                    const float* __restrict__ w,
                    float* __restrict__ out)
{
    __shared__ float  s_in[SIN_FLOATS];       // [ci_local][row][PITCH]
    __shared__ float2 s_w[SW_FLOAT2];         // [ci][co][9], (w,w) duplicated

    const int t  = threadIdx.x;
    const int bx = blockIdx.x;       // 0..15   -> x_base
    const int by = blockIdx.y;       // 0..127  -> y_base
    const int b  = blockIdx.z;       // batch
    const int x_base = bx * TW;
    const int y_base = by * TH;

    // ---- stage all weights once: s_w[ci][co][k] = (W[co][ci][k], same) ----
    for (int i = t; i < SW_FLOAT2; i += THREADS) {
        int ci = i / (COUT * 9);
        int r  = i - ci * (COUT * 9);
        int co = r / 9;
        int k  = r - co * 9;
        float wv = w[((co * CIN + ci) * 9) + k];
        s_w[(ci * COUT + co) * 9 + k] = make_float2(wv, wv);
    }

    // ---- thread mapping ----
    const int grp = t >> 6;          // 0..3 -> cout quarter
    const int p   = t & 63;
    const int ty  = p >> 3;          // 0..7 output row in tile
    const int xg  = p & 7;           // 0..7 x-group
    const int x0  = xg * VEC;        // window lc = x0 .. x0+9 (16B-aligned base)
    const int co0 = grp * NCO;

    ull acc[NCO][4];
    #pragma unroll
    for (int c = 0; c < NCO; c++)
        #pragma unroll
        for (int q = 0; q < 4; q++) acc[c][q] = 0ull;

    const int HTOT = HALF_CI * IN_ROWS * IN_COLS;   // 5280

    #pragma unroll 1
    for (int half = 0; half < 2; half++) {
        // ---- stage this half's input: 8 ci x 10 rows x 66 cols, zero halo ----
        for (int i = t; i < HTOT; i += THREADS) {
            int cil = i / (IN_ROWS * IN_COLS);
            int rem = i - cil * (IN_ROWS * IN_COLS);
            int r   = rem / IN_COLS;
            int lc  = rem - r * IN_COLS;
            int ci  = half * HALF_CI + cil;
            int gy  = y_base + r - 1;
            int gx  = x_base + lc - 1;
            float v = 0.0f;
            if ((unsigned)gy < (unsigned)Hh && (unsigned)gx < (unsigned)Ww)
                v = x[(((size_t)b * CIN + ci) * Hh + gy) * Ww + gx];
            s_in[(cil * IN_ROWS + r) * PITCH + lc] = v;
        }
        __syncthreads();

        // ---- compute over this half's 8 ci ----
        #pragma unroll 1
        for (int cil = 0; cil < HALF_CI; cil++) {
            const float* in_ci = &s_in[(cil * IN_ROWS + ty) * PITCH + x0];
            const float2* w_ci = &s_w[((half * HALF_CI + cil) * COUT + co0) * 9];
            #pragma unroll
            for (int ry = 0; ry < 3; ry++) {
                const float* row = in_ci + ry * PITCH;
                U4 va, vb; U2 vc;
                va.f = *(const float4*)(row);        // v0..v3
                vb.f = *(const float4*)(row + 4);    // v4..v7
                vc.f = *(const float2*)(row + 8);    // v8,v9
                ull pr[9];
                pr[0] = va.u[0];                     // (v0,v1)
                pr[2] = va.u[1];                     // (v2,v3)
                pr[4] = vb.u[0];                     // (v4,v5)
                pr[6] = vb.u[1];                     // (v6,v7)
                pr[8] = vc.u;                        // (v8,v9)
                pr[1] = pack2(va.f.y, va.f.z);       // (v1,v2)
                pr[3] = pack2(va.f.w, vb.f.x);       // (v3,v4)
                pr[5] = pack2(vb.f.y, vb.f.z);       // (v5,v6)
                pr[7] = pack2(vb.f.w, vc.f.x);       // (v7,v8)
                #pragma unroll
                for (int c = 0; c < NCO; c++) {
                    const ull* wp = (const ull*)&w_ci[c * 9 + ry * 3];
                    #pragma unroll
                    for (int kx = 0; kx < 3; kx++) {
                        ull w2 = wp[kx];
                        #pragma unroll
                        for (int q = 0; q < 4; q++)
                            fma2(acc[c][q], pr[kx + 2 * q], w2);
                    }
                }
            }
        }
        __syncthreads();   // protect s_in before next half restages
    }

    // ---- write back: 2x float4 per cout ----
    const int oy = y_base + ty;
    const int ox = x_base + x0;
    #pragma unroll
    for (int c = 0; c < NCO; c++) {
        float* op = &out[(((size_t)b * COUT + (co0 + c)) * Hh + oy) * Ww + ox];
        float r0, r1, r2, r3, r4, r5, r6, r7;
        unpack2(acc[c][0], r0, r1);
        unpack2(acc[c][1], r2, r3);
        unpack2(acc[c][2], r4, r5);
        unpack2(acc[c][3], r6, r7);
        ((float4*)op)[0] = make_float4(r0, r1, r2, r3);
        ((float4*)op)[1] = make_float4(r4, r5, r6, r7);
    }
}

extern "C" void kernel_launch(void* const* d_in, const int* in_sizes, int n_in,
                              void* d_out, int out_size)
{
    const float* x = (const float*)d_in[0];
    const float* w = (const float*)d_in[1];
    float* out = (float*)d_out;

    dim3 grid(Ww / TW, Hh / TH, Bb);   // (16, 128, 8)
    conv3x3_kernel<<<grid, THREADS>>>(x, w, out);
}

// round 10
// speedup vs baseline: 1.0339x; 1.0002x over previous
#include <cuda_runtime.h>
#include <cstdint>

// 3x3 conv, stride 1, pad 1, NCHW fp32. B=8, CIN=COUT=16, H=W=1024.
// v4: identical to v3 except fma2 uses a tied "+l" constraint, eliminating
// the per-FMA accumulator register-pair copies (~1 MOV per FFMA2 in v3).
// Tile 8x64, NCO=4, CIN staged in two 8-ci halves, 3 blocks/SM (24 warps).

#define CIN   16
#define COUT  16
#define Hh    1024
#define Ww    1024
#define Bb    8

#define TH    8           // output rows per block
#define TW    64          // output cols per block
#define VEC   8           // pixels per thread
#define NCO   4           // couts per thread group
#define THREADS 256

#define HALF_CI  8
#define IN_ROWS  (TH + 2)         // 10
#define IN_COLS  (TW + 2)         // 66, lc = gx - x_base + 1
#define PITCH    72               // 288B rows, 16B multiple for LDS.128
#define SIN_FLOATS (HALF_CI * IN_ROWS * PITCH)   // 5760 (23040 B)
#define SW_FLOAT2  (CIN * COUT * 9)              // 2304  (18432 B)

typedef unsigned long long ull;

__device__ __forceinline__ void fma2(ull& d, ull a, ull b) {
    // Tied accumulator: no register-pair copies around the packed FMA.
    asm("fma.rn.f32x2 %0, %1, %2, %0;" : "+l"(d) : "l"(a), "l"(b));
}
__device__ __forceinline__ ull pack2(float lo, float hi) {
    ull r;
    asm("mov.b64 %0, {%1, %2};" : "=l"(r) : "f"(lo), "f"(hi));
    return r;
}
__device__ __forceinline__ void unpack2(ull v, float& lo, float& hi) {
    asm("mov.b64 {%0, %1}, %2;" : "=f"(lo), "=f"(hi) : "l"(v));
}

union U4 { float4 f; ull u[2]; };
union U2 { float2 f; ull u; };

__global__ __launch_bounds__(THREADS, 3)
void conv3x3_kernel(const float* __restrict__ x,
                    const float* __restrict__ w,
                    float* __restrict__ out)
{
    __shared__ float  s_in[SIN_FLOATS];       // [ci_local][row][PITCH]
    __shared__ float2 s_w[SW_FLOAT2];         // [ci][co][9], (w,w) duplicated

    const int t  = threadIdx.x;
    const int bx = blockIdx.x;       // 0..15   -> x_base
    const int by = blockIdx.y;       // 0..127  -> y_base
    const int b  = blockIdx.z;       // batch
    const int x_base = bx * TW;
    const int y_base = by * TH;

    // ---- stage all weights once: s_w[ci][co][k] = (W[co][ci][k], same) ----
    for (int i = t; i < SW_FLOAT2; i += THREADS) {
        int ci = i / (COUT * 9);
        int r  = i - ci * (COUT * 9);
        int co = r / 9;
        int k  = r - co * 9;
        float wv = w[((co * CIN + ci) * 9) + k];
        s_w[(ci * COUT + co) * 9 + k] = make_float2(wv, wv);
    }

    // ---- thread mapping ----
    const int grp = t >> 6;          // 0..3 -> cout quarter
    const int p   = t & 63;
    const int ty  = p >> 3;          // 0..7 output row in tile
    const int xg  = p & 7;           // 0..7 x-group
    const int x0  = xg * VEC;        // window lc = x0 .. x0+9 (16B-aligned base)
    const int co0 = grp * NCO;

    ull acc[NCO][4];
    #pragma unroll
    for (int c = 0; c < NCO; c++)
        #pragma unroll
        for (int q = 0; q < 4; q++) acc[c][q] = 0ull;

    const int HTOT = HALF_CI * IN_ROWS * IN_COLS;   // 5280

    #pragma unroll 1
    for (int half = 0; half < 2; half++) {
        // ---- stage this half's input: 8 ci x 10 rows x 66 cols, zero halo ----
        for (int i = t; i < HTOT; i += THREADS) {
            int cil = i / (IN_ROWS * IN_COLS);
            int rem = i - cil * (IN_ROWS * IN_COLS);
            int r   = rem / IN_COLS;
            int lc  = rem - r * IN_COLS;
            int ci  = half * HALF_CI + cil;
            int gy  = y_base + r - 1;
            int gx  = x_base + lc - 1;
            float v = 0.0f;
            if ((unsigned)gy < (unsigned)Hh && (unsigned)gx < (unsigned)Ww)
                v = x[(((size_t)b * CIN + ci) * Hh + gy) * Ww + gx];
            s_in[(cil * IN_ROWS + r) * PITCH + lc] = v;
        }
        __syncthreads();

        // ---- compute over this half's 8 ci ----
        #pragma unroll 1
        for (int cil = 0; cil < HALF_CI; cil++) {
            const float* in_ci = &s_in[(cil * IN_ROWS + ty) * PITCH + x0];
            const float2* w_ci = &s_w[((half * HALF_CI + cil) * COUT + co0) * 9];
            #pragma unroll
            for (int ry = 0; ry < 3; ry++) {
                const float* row = in_ci + ry * PITCH;
                U4 va, vb; U2 vc;
                va.f = *(const float4*)(row);        // v0..v3
                vb.f = *(const float4*)(row + 4);    // v4..v7
                vc.f = *(const float2*)(row + 8);    // v8,v9
                ull pr[9];
                pr[0] = va.u[0];                     // (v0,v1)
                pr[2] = va.u[1];                     // (v2,v3)
                pr[4] = vb.u[0];                     // (v4,v5)
                pr[6] = vb.u[1];                     // (v6,v7)
                pr[8] = vc.u;                        // (v8,v9)
                pr[1] = pack2(va.f.y, va.f.z);       // (v1,v2)
                pr[3] = pack2(va.f.w, vb.f.x);       // (v3,v4)
                pr[5] = pack2(vb.f.y, vb.f.z);       // (v5,v6)
                pr[7] = pack2(vb.f.w, vc.f.x);       // (v7,v8)
                #pragma unroll
                for (int c = 0; c < NCO; c++) {
                    const ull* wp = (const ull*)&w_ci[c * 9 + ry * 3];
                    #pragma unroll
                    for (int kx = 0; kx < 3; kx++) {
                        ull w2 = wp[kx];
                        #pragma unroll
                        for (int q = 0; q < 4; q++)
                            fma2(acc[c][q], pr[kx + 2 * q], w2);
                    }
                }
            }
        }
        __syncthreads();   // protect s_in before next half restages
    }

    // ---- write back: 2x float4 per cout ----
    const int oy = y_base + ty;
    const int ox = x_base + x0;
    #pragma unroll
    for (int c = 0; c < NCO; c++) {
        float* op = &out[(((size_t)b * COUT + (co0 + c)) * Hh + oy) * Ww + ox];
        float r0, r1, r2, r3, r4, r5, r6, r7;
        unpack2(acc[c][0], r0, r1);
        unpack2(acc[c][1], r2, r3);
        unpack2(acc[c][2], r4, r5);
        unpack2(acc[c][3], r6, r7);
        ((float4*)op)[0] = make_float4(r0, r1, r2, r3);
        ((float4*)op)[1] = make_float4(r4, r5, r6, r7);
    }
}

extern "C" void kernel_launch(void* const* d_in, const int* in_sizes, int n_in,
                              void* d_out, int out_size)
{
    const float* x = (const float*)d_in[0];
    const float* w = (const float*)d_in[1];
    float* out = (float*)d_out;

    dim3 grid(Ww / TW, Hh / TH, Bb);   // (16, 128, 8)
    conv3x3_kernel<<<grid, THREADS>>>(x, w, out);
}